// round 1
// baseline (speedup 1.0000x reference)
#include <cuda_runtime.h>
#include <math.h>

// Shapes (fixed by the reference):
//  B=16, T=32 -> BT=512
//  NP=8 preds, NG=4 gts, J=14 joints, H=256
//  hor_heatmap: (B,T,1,H,H) contiguous == (B,T,H,H) since dim2==1
#define BT      512
#define NPRED   8
#define NGT     4
#define NJ      14
#define HH      256
#define NPERM   1680              // P(8,4) = 8*7*6*5
#define HEAT_N  (512 * 256 * 256) // 33,554,432 elements
#define HEAT_BLOCKS 1024

// Deterministic per-block partials (no float atomics -> bit-stable across graph replays)
__device__ float g_heat_part[HEAT_BLOCKS];
__device__ float g_off_part[BT];
__device__ float g_size_part[BT];
__device__ float g_pose_part[BT];

// ---------------------------------------------------------------------------
// Kernel 1: heatmap MSE partial sums (memory-bound; float4 grid-stride)
// ---------------------------------------------------------------------------
__global__ void k_heat(const float4* __restrict__ a, const float4* __restrict__ b) {
    const int n4 = HEAT_N / 4;
    float acc = 0.f;
    for (int i = blockIdx.x * blockDim.x + threadIdx.x; i < n4;
         i += gridDim.x * blockDim.x) {
        float4 x = a[i];
        float4 y = b[i];
        float dx = x.x - y.x, dy = x.y - y.y, dz = x.z - y.z, dw = x.w - y.w;
        acc += dx * dx + dy * dy + dz * dz + dw * dw;
    }
    __shared__ float s[256];
    s[threadIdx.x] = acc;
    __syncthreads();
    for (int o = 128; o > 0; o >>= 1) {
        if (threadIdx.x < o) s[threadIdx.x] += s[threadIdx.x + o];
        __syncthreads();
    }
    if (threadIdx.x == 0) g_heat_part[blockIdx.x] = s[0];
}

// ---------------------------------------------------------------------------
// Permutation rank -> lexicographic k-permutation of range(8), k=4.
// Mixed-radix divisors (7*6*5, 6*5, 5, 1) match itertools.permutations order.
// ---------------------------------------------------------------------------
__device__ __forceinline__ void decode_perm(int r, int* p) {
    int avail[NPRED];
#pragma unroll
    for (int i = 0; i < NPRED; i++) avail[i] = i;
    const int divs[4] = {210, 30, 5, 1};
    int n = NPRED;
#pragma unroll
    for (int k = 0; k < NGT; k++) {
        int d = r / divs[k];
        r -= d * divs[k];
        p[k] = avail[d];
        for (int m = d; m < n - 1; m++) avail[m] = avail[m + 1];
        n--;
    }
}

// ---------------------------------------------------------------------------
// Kernel 2: per-(b,t) exhaustive Hungarian match (box + pose) and losses.
// One block of 128 threads per (b,t).
// ---------------------------------------------------------------------------
__global__ void __launch_bounds__(128)
k_match(const float* __restrict__ po_all,   // hor_offset  (BT, NP, 2)
        const float* __restrict__ ps_all,   // hor_bsize   (BT, NP, 4)
        const float* __restrict__ pc_all,   // hor_center  (BT, NP, 2)
        const float* __restrict__ sc_all,   // scores      (BT, NP)
        const float* __restrict__ pp_all,   // x_pose3d    (BT, NP, J, 3)
        const float* __restrict__ gs_all,   // gt_boxes_wh (BT, NG, 4)
        const float* __restrict__ go_all,   // gt_offset   (BT, NG, 2)
        const float* __restrict__ gc_all,   // gt_center   (BT, NG, 2)
        const float* __restrict__ gp_all)   // gt_pose3d   (BT, NG, J, 3)
{
    const int bt = blockIdx.x;
    const int t  = threadIdx.x;

    const float* pc = pc_all + bt * NPRED * 2;
    const float* gc = gc_all + bt * NGT * 2;
    const float* sc = sc_all + bt * NPRED;
    const float* pp = pp_all + bt * NPRED * NJ * 3;
    const float* gp = gp_all + bt * NGT * NJ * 3;

    __shared__ float Cb[NPRED][NGT];
    __shared__ float Cp[NPRED][NGT];
    __shared__ float sbv[128], spv[128];
    __shared__ int   sbr[128], spr[128];

    // Cost matrices: 32 threads, one (i,j) entry each.
    if (t < NPRED * NGT) {
        int i = t / NGT, j = t % NGT;
        float dx = pc[i * 2 + 0] - gc[j * 2 + 0];
        float dy = pc[i * 2 + 1] - gc[j * 2 + 1];
        Cb[i][j] = sqrtf(dx * dx + dy * dy) - sc[i];
        float s = 0.f;
        const float* pi = pp + i * NJ * 3;
        const float* gj = gp + j * NJ * 3;
#pragma unroll
        for (int k = 0; k < NJ * 3; k++) {
            float d = pi[k] - gj[k];
            s += d * d;
        }
        Cp[i][j] = sqrtf(s);
    }
    __syncthreads();

    // Exhaustive sweep over 1680 lexicographic permutation ranks.
    float bv = INFINITY, pv = INFINITY;
    int   br = 0,        pr = 0;
    for (int r = t; r < NPERM; r += 128) {
        int p[4];
        decode_perm(r, p);
        float tb = Cb[p[0]][0] + Cb[p[1]][1] + Cb[p[2]][2] + Cb[p[3]][3];
        if (tb < bv) { bv = tb; br = r; }
        float tp = Cp[p[0]][0] + Cp[p[1]][1] + Cp[p[2]][2] + Cp[p[3]][3];
        if (tp < pv) { pv = tp; pr = r; }
    }
    sbv[t] = bv; sbr[t] = br;
    spv[t] = pv; spr[t] = pr;
    __syncthreads();

    if (t == 0) {
        // First-min tiebreak on rank to mirror jnp.argmin semantics.
        float bbv = sbv[0]; int bbr = sbr[0];
        float bpv = spv[0]; int bpr = spr[0];
        for (int k = 1; k < 128; k++) {
            if (sbv[k] < bbv || (sbv[k] == bbv && sbr[k] < bbr)) { bbv = sbv[k]; bbr = sbr[k]; }
            if (spv[k] < bpv || (spv[k] == bpv && spr[k] < bpr)) { bpv = spv[k]; bpr = spr[k]; }
        }

        const float* po = po_all + bt * NPRED * 2;
        const float* go = go_all + bt * NGT * 2;
        const float* ps = ps_all + bt * NPRED * 4;
        const float* gs = gs_all + bt * NGT * 4;

        int pb[4];
        decode_perm(bbr, pb);
        float off = 0.f, sz = 0.f;
#pragma unroll
        for (int j = 0; j < NGT; j++) {
            int i = pb[j];
            off += 0.5f * (fabsf(po[i * 2 + 0] - go[j * 2 + 0]) +
                           fabsf(po[i * 2 + 1] - go[j * 2 + 1]));
            float s4 = 0.f;
#pragma unroll
            for (int k = 0; k < 4; k++) s4 += fabsf(ps[i * 4 + k] - gs[j * 4 + k]);
            sz += 0.25f * s4;
        }

        int pq[4];
        decode_perm(bpr, pq);
        float pl = 0.f;
#pragma unroll
        for (int j = 0; j < NGT; j++) {
            int i = pq[j];
            const float* pi = pp + i * NJ * 3;
            const float* gj = gp + j * NJ * 3;
#pragma unroll
            for (int k = 0; k < NJ * 3; k++) {
                float d = pi[k] - gj[k];
                pl += d * d;
            }
        }

        g_off_part[bt]  = off;
        g_size_part[bt] = sz;
        g_pose_part[bt] = pl;
    }
}

// ---------------------------------------------------------------------------
// Kernel 3: combine partials into the scalar loss.
// loss = mean(heat) + off/BT + size/BT + pose/(BT*NP*J)
// ---------------------------------------------------------------------------
__global__ void k_final(float* __restrict__ out) {
    const float inv_heat = 1.f / (float)HEAT_N;
    const float inv_bt   = 1.f / (float)BT;
    const float inv_pose = 1.f / (float)(BT * NPRED * NJ);

    int t = threadIdx.x;
    float v = 0.f;
    for (int i = t; i < HEAT_BLOCKS; i += 256) v += g_heat_part[i] * inv_heat;
    for (int i = t; i < BT; i += 256)
        v += (g_off_part[i] + g_size_part[i]) * inv_bt + g_pose_part[i] * inv_pose;

    __shared__ float s[256];
    s[t] = v;
    __syncthreads();
    for (int o = 128; o > 0; o >>= 1) {
        if (t < o) s[t] += s[t + o];
        __syncthreads();
    }
    if (t == 0) out[0] = s[0];
}

// ---------------------------------------------------------------------------
extern "C" void kernel_launch(void* const* d_in, const int* in_sizes, int n_in,
                              void* d_out, int out_size) {
    const float* hor_heatmap = (const float*)d_in[0];
    const float* hor_offset  = (const float*)d_in[1];
    const float* hor_bsize   = (const float*)d_in[2];
    const float* hor_center  = (const float*)d_in[3];
    const float* scores      = (const float*)d_in[4];
    const float* x_pose3d    = (const float*)d_in[5];
    const float* gt_heatmap  = (const float*)d_in[6];
    const float* gt_boxes_wh = (const float*)d_in[7];
    const float* gt_offset   = (const float*)d_in[8];
    const float* gt_center   = (const float*)d_in[9];
    const float* gt_pose3d   = (const float*)d_in[10];

    k_heat<<<HEAT_BLOCKS, 256>>>((const float4*)hor_heatmap, (const float4*)gt_heatmap);
    k_match<<<BT, 128>>>(hor_offset, hor_bsize, hor_center, scores, x_pose3d,
                         gt_boxes_wh, gt_offset, gt_center, gt_pose3d);
    k_final<<<1, 256>>>((float*)d_out);
}

// round 3
// speedup vs baseline: 1.6650x; 1.6650x over previous
#include <cuda_runtime.h>
#include <math.h>

// Shapes fixed by the reference:
//  B=16,T=32 -> BT=512 ; NP=8, NG=4, J=14, H=256
#define BT      512
#define NPRED   8
#define NGT     4
#define NJ      14
#define NPERM   1680                 // P(8,4)
#define HEAT_N  (512 * 256 * 256)    // 33,554,432 floats
#define N4      (HEAT_N / 4)         // 8,388,608 float4
#define NBLK    1024
#define NMATCH  512
#define WM      7                    // heat-work weight for match blocks
#define WH      8                    // heat-work weight for heat-only blocks
#define TOTW    (NMATCH * WM + (NBLK - NMATCH) * WH)   // 7680

#define INV_HEAT (1.0f / (float)HEAT_N)
#define INV_BT   (1.0f / 512.0f)
#define INV_POSE (1.0f / (512.0f * 8.0f * 14.0f))

__device__ float        g_part[NBLK];   // per-block heat partial
__device__ float        g_match[BT];    // per-(b,t) combined match contribution
__device__ unsigned int g_count;        // completion counter (self-resetting)

// Monotone float->uint map: equal floats -> equal keys, order preserved.
__device__ __forceinline__ unsigned f2ord(float v) {
    unsigned u = __float_as_uint(v);
    return (u & 0x80000000u) ? ~u : (u | 0x80000000u);
}

__device__ __forceinline__ unsigned long long umin64(unsigned long long a,
                                                     unsigned long long b) {
    return a < b ? a : b;
}

// Lexicographic rank -> k-permutation of range(8), k=4. Register-only
// (bitmask + d-th-set-bit), matches itertools.permutations order.
__device__ __forceinline__ void decode_perm(int r, int* p) {
    const int divs[4] = {210, 30, 5, 1};
    unsigned mask = 0xFFu;
#pragma unroll
    for (int k = 0; k < 4; k++) {
        int d = r / divs[k];
        r -= d * divs[k];
        unsigned m = mask;
#pragma unroll
        for (int q = 0; q < 7; q++)
            if (q < d) m &= (m - 1);   // clear d lowest set bits
        int idx = __ffs(m) - 1;
        mask &= ~(1u << idx);
        p[k] = idx;
    }
}

__global__ void __launch_bounds__(256, 7)
k_fused(const float4* __restrict__ ha,   // hor_heatmap as float4
        const float4* __restrict__ hb,   // gt_heatmap  as float4
        const float* __restrict__ po_all,   // hor_offset  (BT,8,2)
        const float* __restrict__ ps_all,   // hor_bsize   (BT,8,4)
        const float* __restrict__ pc_all,   // hor_center  (BT,8,2)
        const float* __restrict__ sc_all,   // scores      (BT,8)
        const float* __restrict__ pp_all,   // x_pose3d    (BT,8,14,3)
        const float* __restrict__ gs_all,   // gt_boxes_wh (BT,4,4)
        const float* __restrict__ go_all,   // gt_offset   (BT,4,2)
        const float* __restrict__ gc_all,   // gt_center   (BT,4,2)
        const float* __restrict__ gp_all,   // gt_pose3d   (BT,4,14,3)
        float* __restrict__ out)
{
    const int bid = blockIdx.x;
    const int t   = threadIdx.x;

    __shared__ float Cb[NPRED][NGT];
    __shared__ float Cp[NPRED][NGT];
    __shared__ unsigned long long wmin[2][8];
    __shared__ int   s_pb[4], s_pq[4];
    __shared__ float sred[256];
    __shared__ bool  isLast;

    // ------------------------------------------------------------------
    // Phase 1 (blocks 0..511): exhaustive Hungarian match for bt = bid.
    // ------------------------------------------------------------------
    if (bid < NMATCH) {
        const int bt = bid;
        const float* pc = pc_all + bt * 16;
        const float* gc = gc_all + bt * 8;
        const float* sc = sc_all + bt * 8;
        const float* pp = pp_all + bt * NPRED * 42;
        const float* gp = gp_all + bt * NGT * 42;

        // Cost matrices: 32 threads, one (i,j) each.
        if (t < 32) {
            int i = t >> 2, j = t & 3;
            float dx = pc[2 * i]     - gc[2 * j];
            float dy = pc[2 * i + 1] - gc[2 * j + 1];
            Cb[i][j] = sqrtf(dx * dx + dy * dy) - sc[i];
            float s = 0.f;
            const float* pi = pp + i * 42;
            const float* gj = gp + j * 42;
#pragma unroll
            for (int k = 0; k < 42; k++) {
                float d = pi[k] - gj[k];
                s += d * d;
            }
            Cp[i][j] = sqrtf(s);
        }
        __syncthreads();

        // Sweep all 1680 ranks; min over (orderedFloat, rank) keys gives
        // exact first-min argmin semantics.
        unsigned long long kb = ~0ull, kp = ~0ull;
        for (int r = t; r < NPERM; r += 256) {
            int p[4];
            decode_perm(r, p);
            float tb = Cb[p[0]][0] + Cb[p[1]][1] + Cb[p[2]][2] + Cb[p[3]][3];
            float tp = Cp[p[0]][0] + Cp[p[1]][1] + Cp[p[2]][2] + Cp[p[3]][3];
            kb = umin64(kb, ((unsigned long long)f2ord(tb) << 32) | (unsigned)r);
            kp = umin64(kp, ((unsigned long long)f2ord(tp) << 32) | (unsigned)r);
        }
#pragma unroll
        for (int o = 16; o > 0; o >>= 1) {
            kb = umin64(kb, __shfl_down_sync(0xffffffffu, kb, o));
            kp = umin64(kp, __shfl_down_sync(0xffffffffu, kp, o));
        }
        if ((t & 31) == 0) { wmin[0][t >> 5] = kb; wmin[1][t >> 5] = kp; }
        __syncthreads();
        if (t == 0) {
            unsigned long long b = wmin[0][0], q = wmin[1][0];
#pragma unroll
            for (int w = 1; w < 8; w++) {
                b = umin64(b, wmin[0][w]);
                q = umin64(q, wmin[1][w]);
            }
            int pb[4], pq[4];
            decode_perm((int)(b & 0xFFFFFFFFu), pb);
            decode_perm((int)(q & 0xFFFFFFFFu), pq);
#pragma unroll
            for (int j = 0; j < 4; j++) { s_pb[j] = pb[j]; s_pq[j] = pq[j]; }
        }
        __syncthreads();

        // Tail losses: warp 0, parallel over terms, shuffle-sum (fixed order).
        if (t < 32) {
            float pose_acc = 0.f, box_acc = 0.f;
            // pose: 4*42 = 168 squared diffs
            for (int idx = t; idx < 168; idx += 32) {
                int j = idx / 42, k = idx - j * 42;
                float d = pp[s_pq[j] * 42 + k] - gp[idx];
                pose_acc += d * d;
            }
            // offset (0.5*L1 over 2) + size (0.25*L1 over 4): 24 terms
            if (t < 24) {
                int j = t / 6, w = t - j * 6;
                int i = s_pb[j];
                if (w < 2) {
                    box_acc = 0.5f * fabsf(po_all[bt * 16 + i * 2 + w] -
                                           go_all[bt * 8  + j * 2 + w]);
                } else {
                    int k = w - 2;
                    box_acc = 0.25f * fabsf(ps_all[bt * 32 + i * 4 + k] -
                                            gs_all[bt * 16 + j * 4 + k]);
                }
            }
            float v = pose_acc * INV_POSE + box_acc * INV_BT;
#pragma unroll
            for (int o = 16; o > 0; o >>= 1)
                v += __shfl_down_sync(0xffffffffu, v, o);
            if (t == 0) g_match[bt] = v;
        }
        __syncthreads();
    }

    // ------------------------------------------------------------------
    // Phase 2 (all blocks): heatmap MSE over a statically skewed range.
    // Match blocks get 7/8 of a heat-only block's share.
    // ------------------------------------------------------------------
    {
        long long cw0 = (bid < NMATCH)
                            ? (long long)bid * WM
                            : (long long)NMATCH * WM + (long long)(bid - NMATCH) * WH;
        long long cw1 = cw0 + ((bid < NMATCH) ? WM : WH);
        long long s = cw0 * (long long)N4 / TOTW;
        long long e = cw1 * (long long)N4 / TOTW;

        float a0 = 0.f, a1 = 0.f, a2 = 0.f, a3 = 0.f;
        long long base = s;
        for (; base + 1024 <= e; base += 1024) {
            long long i0 = base + t;
            float4 x0 = __ldcs(ha + i0),       y0 = __ldcs(hb + i0);
            float4 x1 = __ldcs(ha + i0 + 256), y1 = __ldcs(hb + i0 + 256);
            float4 x2 = __ldcs(ha + i0 + 512), y2 = __ldcs(hb + i0 + 512);
            float4 x3 = __ldcs(ha + i0 + 768), y3 = __ldcs(hb + i0 + 768);
            float d;
            d = x0.x - y0.x; a0 += d * d;  d = x0.y - y0.y; a0 += d * d;
            d = x0.z - y0.z; a0 += d * d;  d = x0.w - y0.w; a0 += d * d;
            d = x1.x - y1.x; a1 += d * d;  d = x1.y - y1.y; a1 += d * d;
            d = x1.z - y1.z; a1 += d * d;  d = x1.w - y1.w; a1 += d * d;
            d = x2.x - y2.x; a2 += d * d;  d = x2.y - y2.y; a2 += d * d;
            d = x2.z - y2.z; a2 += d * d;  d = x2.w - y2.w; a2 += d * d;
            d = x3.x - y3.x; a3 += d * d;  d = x3.y - y3.y; a3 += d * d;
            d = x3.z - y3.z; a3 += d * d;  d = x3.w - y3.w; a3 += d * d;
        }
        for (long long i = base + t; i < e; i += 256) {
            float4 x = __ldcs(ha + i), y = __ldcs(hb + i);
            float d;
            d = x.x - y.x; a0 += d * d;  d = x.y - y.y; a0 += d * d;
            d = x.z - y.z; a0 += d * d;  d = x.w - y.w; a0 += d * d;
        }

        sred[t] = (a0 + a1) + (a2 + a3);
        __syncthreads();
#pragma unroll
        for (int o = 128; o > 0; o >>= 1) {
            if (t < o) sred[t] += sred[t + o];
            __syncthreads();
        }
        if (t == 0) g_part[bid] = sred[0];
    }

    // ------------------------------------------------------------------
    // Phase 3: last block to arrive does the final combine
    // (classic threadFenceReduction: writer fence + atomic ticket).
    // ------------------------------------------------------------------
    if (t == 0) {
        __threadfence();
        unsigned old = atomicAdd(&g_count, 1u);
        isLast = (old == NBLK - 1);
    }
    __syncthreads();

    if (isLast) {
        __threadfence();
        float v = 0.f;
        for (int i = t; i < NBLK; i += 256) v += g_part[i] * INV_HEAT;
        for (int i = t; i < BT;   i += 256) v += g_match[i];
        __syncthreads();            // sred reuse barrier
        sred[t] = v;
        __syncthreads();
#pragma unroll
        for (int o = 128; o > 0; o >>= 1) {
            if (t < o) sred[t] += sred[t + o];
            __syncthreads();
        }
        if (t == 0) {
            out[0]  = sred[0];
            g_count = 0;            // reset for next graph replay
        }
    }
}

extern "C" void kernel_launch(void* const* d_in, const int* in_sizes, int n_in,
                              void* d_out, int out_size) {
    const float* hor_heatmap = (const float*)d_in[0];
    const float* hor_offset  = (const float*)d_in[1];
    const float* hor_bsize   = (const float*)d_in[2];
    const float* hor_center  = (const float*)d_in[3];
    const float* scores      = (const float*)d_in[4];
    const float* x_pose3d    = (const float*)d_in[5];
    const float* gt_heatmap  = (const float*)d_in[6];
    const float* gt_boxes_wh = (const float*)d_in[7];
    const float* gt_offset   = (const float*)d_in[8];
    const float* gt_center   = (const float*)d_in[9];
    const float* gt_pose3d   = (const float*)d_in[10];

    k_fused<<<NBLK, 256>>>((const float4*)hor_heatmap, (const float4*)gt_heatmap,
                           hor_offset, hor_bsize, hor_center, scores, x_pose3d,
                           gt_boxes_wh, gt_offset, gt_center, gt_pose3d,
                           (float*)d_out);
}

// round 4
// speedup vs baseline: 1.6733x; 1.0050x over previous
#include <cuda_runtime.h>
#include <math.h>

// Shapes fixed by the reference:
//  B=16,T=32 -> BT=512 ; NP=8, NG=4, J=14, H=256
#define BT      512
#define NPRED   8
#define NGT     4
#define NJ      14
#define NPERM   1680                 // P(8,4)
#define HEAT_N  (512 * 256 * 256)    // 33,554,432 floats
#define N4      (HEAT_N / 4)         // 8,388,608 float4
#define NBLK    1024
#define NMATCH  512
#define WM      7                    // heat-work weight for match blocks
#define WH      8                    // heat-work weight for heat-only blocks
#define TOTW    (NMATCH * WM + (NBLK - NMATCH) * WH)   // 7680

#define INV_HEAT (1.0f / (float)HEAT_N)
#define INV_BT   (1.0f / 512.0f)
#define INV_POSE (1.0f / (512.0f * 8.0f * 14.0f))

__device__ float        g_part[NBLK];   // per-block heat partial
__device__ float        g_match[BT];    // per-(b,t) combined match contribution
__device__ unsigned int g_count;        // completion counter (self-resetting)

// Monotone float->uint map: equal floats -> equal keys, order preserved.
__device__ __forceinline__ unsigned f2ord(float v) {
    unsigned u = __float_as_uint(v);
    return (u & 0x80000000u) ? ~u : (u | 0x80000000u);
}

__device__ __forceinline__ unsigned long long umin64(unsigned long long a,
                                                     unsigned long long b) {
    return a < b ? a : b;
}

// Lexicographic rank -> k-permutation of range(8), k=4. Register-only
// (bitmask + d-th-set-bit), matches itertools.permutations order.
__device__ __forceinline__ void decode_perm(int r, int* p) {
    const int divs[4] = {210, 30, 5, 1};
    unsigned mask = 0xFFu;
#pragma unroll
    for (int k = 0; k < 4; k++) {
        int d = r / divs[k];
        r -= d * divs[k];
        unsigned m = mask;
#pragma unroll
        for (int q = 0; q < 7; q++)
            if (q < d) m &= (m - 1);   // clear d lowest set bits
        int idx = __ffs(m) - 1;
        mask &= ~(1u << idx);
        p[k] = idx;
    }
}

__global__ void __launch_bounds__(256, 7)
k_fused(const float4* __restrict__ ha,   // hor_heatmap as float4
        const float4* __restrict__ hb,   // gt_heatmap  as float4
        const float* __restrict__ po_all,   // hor_offset  (BT,8,2)
        const float* __restrict__ ps_all,   // hor_bsize   (BT,8,4)
        const float* __restrict__ pc_all,   // hor_center  (BT,8,2)
        const float* __restrict__ sc_all,   // scores      (BT,8)
        const float* __restrict__ pp_all,   // x_pose3d    (BT,8,14,3)
        const float* __restrict__ gs_all,   // gt_boxes_wh (BT,4,4)
        const float* __restrict__ go_all,   // gt_offset   (BT,4,2)
        const float* __restrict__ gc_all,   // gt_center   (BT,4,2)
        const float* __restrict__ gp_all,   // gt_pose3d   (BT,4,14,3)
        float* __restrict__ out)
{
    const int bid = blockIdx.x;
    const int t   = threadIdx.x;

    __shared__ float Cb[NPRED][NGT];
    __shared__ float Cp[NPRED][NGT];
    __shared__ unsigned long long wmin[2][8];
    __shared__ int   s_pb[4], s_pq[4];
    __shared__ float sred[256];
    __shared__ bool  isLast;

    // ------------------------------------------------------------------
    // Phase 1 (blocks 0..511): exhaustive Hungarian match for bt = bid.
    // ------------------------------------------------------------------
    if (bid < NMATCH) {
        const int bt = bid;
        const float* pc = pc_all + bt * 16;
        const float* gc = gc_all + bt * 8;
        const float* sc = sc_all + bt * 8;
        const float* pp = pp_all + bt * NPRED * 42;
        const float* gp = gp_all + bt * NGT * 42;

        // Cost matrices: 32 threads, one (i,j) each.
        if (t < 32) {
            int i = t >> 2, j = t & 3;
            float dx = pc[2 * i]     - gc[2 * j];
            float dy = pc[2 * i + 1] - gc[2 * j + 1];
            Cb[i][j] = sqrtf(dx * dx + dy * dy) - sc[i];
            float s = 0.f;
            const float* pi = pp + i * 42;
            const float* gj = gp + j * 42;
#pragma unroll
            for (int k = 0; k < 42; k++) {
                float d = pi[k] - gj[k];
                s += d * d;
            }
            Cp[i][j] = sqrtf(s);
        }
        __syncthreads();

        // Sweep all 1680 ranks; min over (orderedFloat, rank) keys gives
        // exact first-min argmin semantics.
        unsigned long long kb = ~0ull, kp = ~0ull;
        for (int r = t; r < NPERM; r += 256) {
            int p[4];
            decode_perm(r, p);
            float tb = Cb[p[0]][0] + Cb[p[1]][1] + Cb[p[2]][2] + Cb[p[3]][3];
            float tp = Cp[p[0]][0] + Cp[p[1]][1] + Cp[p[2]][2] + Cp[p[3]][3];
            kb = umin64(kb, ((unsigned long long)f2ord(tb) << 32) | (unsigned)r);
            kp = umin64(kp, ((unsigned long long)f2ord(tp) << 32) | (unsigned)r);
        }
#pragma unroll
        for (int o = 16; o > 0; o >>= 1) {
            kb = umin64(kb, __shfl_down_sync(0xffffffffu, kb, o));
            kp = umin64(kp, __shfl_down_sync(0xffffffffu, kp, o));
        }
        if ((t & 31) == 0) { wmin[0][t >> 5] = kb; wmin[1][t >> 5] = kp; }
        __syncthreads();
        if (t == 0) {
            unsigned long long b = wmin[0][0], q = wmin[1][0];
#pragma unroll
            for (int w = 1; w < 8; w++) {
                b = umin64(b, wmin[0][w]);
                q = umin64(q, wmin[1][w]);
            }
            int pb[4], pq[4];
            decode_perm((int)(b & 0xFFFFFFFFu), pb);
            decode_perm((int)(q & 0xFFFFFFFFu), pq);
#pragma unroll
            for (int j = 0; j < 4; j++) { s_pb[j] = pb[j]; s_pq[j] = pq[j]; }
        }
        __syncthreads();

        // Tail losses: warp 0, parallel over terms, shuffle-sum (fixed order).
        if (t < 32) {
            float pose_acc = 0.f, box_acc = 0.f;
            // pose: 4*42 = 168 squared diffs
            for (int idx = t; idx < 168; idx += 32) {
                int j = idx / 42, k = idx - j * 42;
                float d = pp[s_pq[j] * 42 + k] - gp[idx];
                pose_acc += d * d;
            }
            // offset (0.5*L1 over 2) + size (0.25*L1 over 4): 24 terms
            if (t < 24) {
                int j = t / 6, w = t - j * 6;
                int i = s_pb[j];
                if (w < 2) {
                    box_acc = 0.5f * fabsf(po_all[bt * 16 + i * 2 + w] -
                                           go_all[bt * 8  + j * 2 + w]);
                } else {
                    int k = w - 2;
                    box_acc = 0.25f * fabsf(ps_all[bt * 32 + i * 4 + k] -
                                            gs_all[bt * 16 + j * 4 + k]);
                }
            }
            float v = pose_acc * INV_POSE + box_acc * INV_BT;
#pragma unroll
            for (int o = 16; o > 0; o >>= 1)
                v += __shfl_down_sync(0xffffffffu, v, o);
            if (t == 0) g_match[bt] = v;
        }
        __syncthreads();
    }

    // ------------------------------------------------------------------
    // Phase 2 (all blocks): heatmap MSE over a statically skewed range.
    // Match blocks get 7/8 of a heat-only block's share.
    // ------------------------------------------------------------------
    {
        long long cw0 = (bid < NMATCH)
                            ? (long long)bid * WM
                            : (long long)NMATCH * WM + (long long)(bid - NMATCH) * WH;
        long long cw1 = cw0 + ((bid < NMATCH) ? WM : WH);
        long long s = cw0 * (long long)N4 / TOTW;
        long long e = cw1 * (long long)N4 / TOTW;

        float a0 = 0.f, a1 = 0.f, a2 = 0.f, a3 = 0.f;
        long long base = s;
        for (; base + 1024 <= e; base += 1024) {
            long long i0 = base + t;
            float4 x0 = __ldcs(ha + i0),       y0 = __ldcs(hb + i0);
            float4 x1 = __ldcs(ha + i0 + 256), y1 = __ldcs(hb + i0 + 256);
            float4 x2 = __ldcs(ha + i0 + 512), y2 = __ldcs(hb + i0 + 512);
            float4 x3 = __ldcs(ha + i0 + 768), y3 = __ldcs(hb + i0 + 768);
            float d;
            d = x0.x - y0.x; a0 += d * d;  d = x0.y - y0.y; a0 += d * d;
            d = x0.z - y0.z; a0 += d * d;  d = x0.w - y0.w; a0 += d * d;
            d = x1.x - y1.x; a1 += d * d;  d = x1.y - y1.y; a1 += d * d;
            d = x1.z - y1.z; a1 += d * d;  d = x1.w - y1.w; a1 += d * d;
            d = x2.x - y2.x; a2 += d * d;  d = x2.y - y2.y; a2 += d * d;
            d = x2.z - y2.z; a2 += d * d;  d = x2.w - y2.w; a2 += d * d;
            d = x3.x - y3.x; a3 += d * d;  d = x3.y - y3.y; a3 += d * d;
            d = x3.z - y3.z; a3 += d * d;  d = x3.w - y3.w; a3 += d * d;
        }
        for (long long i = base + t; i < e; i += 256) {
            float4 x = __ldcs(ha + i), y = __ldcs(hb + i);
            float d;
            d = x.x - y.x; a0 += d * d;  d = x.y - y.y; a0 += d * d;
            d = x.z - y.z; a0 += d * d;  d = x.w - y.w; a0 += d * d;
        }

        sred[t] = (a0 + a1) + (a2 + a3);
        __syncthreads();
#pragma unroll
        for (int o = 128; o > 0; o >>= 1) {
            if (t < o) sred[t] += sred[t + o];
            __syncthreads();
        }
        if (t == 0) g_part[bid] = sred[0];
    }

    // ------------------------------------------------------------------
    // Phase 3: last block to arrive does the final combine
    // (classic threadFenceReduction: writer fence + atomic ticket).
    // ------------------------------------------------------------------
    if (t == 0) {
        __threadfence();
        unsigned old = atomicAdd(&g_count, 1u);
        isLast = (old == NBLK - 1);
    }
    __syncthreads();

    if (isLast) {
        __threadfence();
        float v = 0.f;
        for (int i = t; i < NBLK; i += 256) v += g_part[i] * INV_HEAT;
        for (int i = t; i < BT;   i += 256) v += g_match[i];
        __syncthreads();            // sred reuse barrier
        sred[t] = v;
        __syncthreads();
#pragma unroll
        for (int o = 128; o > 0; o >>= 1) {
            if (t < o) sred[t] += sred[t + o];
            __syncthreads();
        }
        if (t == 0) {
            out[0]  = sred[0];
            g_count = 0;            // reset for next graph replay
        }
    }
}

extern "C" void kernel_launch(void* const* d_in, const int* in_sizes, int n_in,
                              void* d_out, int out_size) {
    const float* hor_heatmap = (const float*)d_in[0];
    const float* hor_offset  = (const float*)d_in[1];
    const float* hor_bsize   = (const float*)d_in[2];
    const float* hor_center  = (const float*)d_in[3];
    const float* scores      = (const float*)d_in[4];
    const float* x_pose3d    = (const float*)d_in[5];
    const float* gt_heatmap  = (const float*)d_in[6];
    const float* gt_boxes_wh = (const float*)d_in[7];
    const float* gt_offset   = (const float*)d_in[8];
    const float* gt_center   = (const float*)d_in[9];
    const float* gt_pose3d   = (const float*)d_in[10];

    k_fused<<<NBLK, 256>>>((const float4*)hor_heatmap, (const float4*)gt_heatmap,
                           hor_offset, hor_bsize, hor_center, scores, x_pose3d,
                           gt_boxes_wh, gt_offset, gt_center, gt_pose3d,
                           (float*)d_out);
}